// round 5
// baseline (speedup 1.0000x reference)
#include <cuda_runtime.h>
#include <cuda_bf16.h>

#define NN 131072
#define EE 2097152

// ---------------- device scratch (static; no allocation allowed) ----------------
__device__ float g_dis[NN];            // degree accumulator -> rsqrt(deg)
__device__ int   g_cnt[NN];            // in-degree histogram
__device__ int   g_rowptr[NN];         // exclusive scan of g_cnt
__device__ int   g_cur[NN];            // scatter cursor
__device__ int   g_blksum[128];
__device__ int   g_blkoff[128];
__device__ int2  g_csr[EE];            // (src, __float_as_int(norm)), grouped by dst
__device__ float g_h1[NN * 128];       // relu(agg(x) @ W1 + b1)
__device__ float g_h2t[NN * 64];       // h1 @ W2

// ---------------- init + degree/histogram ----------------
__global__ void k_init() {
    int i = blockIdx.x * blockDim.x + threadIdx.x;
    if (i < NN) { g_dis[i] = 1.0f; g_cnt[i] = 0; }   // self-loop weight = 1
}

__global__ void k_deg_hist(const int* __restrict__ ei, const float* __restrict__ ew) {
    int e = blockIdx.x * blockDim.x + threadIdx.x;
    if (e < EE) {
        int d = ei[EE + e];
        atomicAdd(&g_dis[d], ew[e]);
        atomicAdd(&g_cnt[d], 1);
    }
}

// ---------------- exclusive scan of g_cnt (128 blocks x 1024 elems) ----------------
__global__ void k_scan1() {
    __shared__ int warp_s[8];
    int b = blockIdx.x, t = threadIdx.x;
    int base = b * 1024 + t * 4;
    int4 c = *(const int4*)&g_cnt[base];
    int s0 = c.x, s1 = s0 + c.y, s2 = s1 + c.z, s3 = s2 + c.w;
    int tsum = s3;
    int lane = t & 31, warp = t >> 5;
    int v = tsum;
    #pragma unroll
    for (int off = 1; off < 32; off <<= 1) {
        int u = __shfl_up_sync(0xffffffffu, v, off);
        if (lane >= off) v += u;
    }
    if (lane == 31) warp_s[warp] = v;
    __syncthreads();
    if (t < 8) {
        int x = warp_s[t];
        #pragma unroll
        for (int off = 1; off < 8; off <<= 1) {
            int u = __shfl_up_sync(0xffu, x, off);
            if (t >= off) x += u;
        }
        warp_s[t] = x;
    }
    __syncthreads();
    int woff = (warp > 0) ? warp_s[warp - 1] : 0;
    int texcl = woff + v - tsum;
    g_rowptr[base + 0] = texcl;
    g_rowptr[base + 1] = texcl + s0;
    g_rowptr[base + 2] = texcl + s1;
    g_rowptr[base + 3] = texcl + s2;
    if (t == 255) g_blksum[b] = woff + v;
}

__global__ void k_scan2() {
    __shared__ int sh[128];
    int t = threadIdx.x;
    int v = g_blksum[t];
    sh[t] = v;
    __syncthreads();
    for (int off = 1; off < 128; off <<= 1) {
        int u = (t >= off) ? sh[t - off] : 0;
        __syncthreads();
        sh[t] += u;
        __syncthreads();
    }
    g_blkoff[t] = sh[t] - v;   // exclusive
}

__global__ void k_scan3_dis() {
    int i = blockIdx.x * blockDim.x + threadIdx.x;
    if (i < NN) {
        int r = g_rowptr[i] + g_blkoff[i >> 10];
        g_rowptr[i] = r;
        g_cur[i] = r;
        g_dis[i] = rsqrtf(g_dis[i]);     // deg >= 1 (self-loop)
    }
}

// ---------------- scatter edges into CSR, norm computed inline ----------------
__global__ void k_scatter(const int* __restrict__ ei, const float* __restrict__ ew) {
    int e = blockIdx.x * blockDim.x + threadIdx.x;
    if (e >= EE) return;
    int s = ei[e], d = ei[EE + e];
    float nrm = g_dis[s] * ew[e] * g_dis[d];
    int pos = atomicAdd(&g_cur[d], 1);
    g_csr[pos] = make_int2(s, __float_as_int(nrm));
}

// ---------------- per-warp CSR aggregation of one node (64 feats, float2/lane) ----------
__device__ __forceinline__ float2 agg_node(const float2* __restrict__ X2, int node, int lane) {
    float sn = g_dis[node];
    sn = sn * sn;
    float2 xs = X2[node * 32 + lane];
    float2 acc = make_float2(sn * xs.x, sn * xs.y);
    int beg = g_rowptr[node];
    int end = beg + g_cnt[node];
    #pragma unroll 4
    for (int j = beg; j < end; j++) {
        int2 pr = g_csr[j];                       // uniform -> broadcast
        float nrm = __int_as_float(pr.y);
        float2 v = X2[pr.x * 32 + lane];          // coalesced 256B gather
        acc.x = fmaf(nrm, v.x, acc.x);
        acc.y = fmaf(nrm, v.y, acc.y);
    }
    return acc;
}

// ---------------- fused: agg(x) -> shared -> GEMM 64->128 + bias + relu ----------------
// Block: 64 nodes, 256 threads. Phase A: each warp aggregates 8 nodes into sA.
// Phase B: GEMM. Warp lanes share rows (rg = tid>>5), so sA reads are broadcasts.
__global__ void agg_gemm1(const float* __restrict__ X, const float* __restrict__ W,
                          const float* __restrict__ bias, float* __restrict__ Y) {
    __shared__ float2 sA[64][33];                 // node-major, padded
    int tid = threadIdx.x;
    int warp = tid >> 5, lane = tid & 31;
    int row0 = blockIdx.x * 64;
    const float2* X2 = (const float2*)X;

    #pragma unroll
    for (int i = 0; i < 8; i++) {
        int r = warp * 8 + i;
        sA[r][lane] = agg_node(X2, row0 + r, lane);
    }
    __syncthreads();

    const float* sAf = (const float*)sA;          // row stride 66 floats
    int cg = tid & 31;                            // 32 col-groups x 4 cols = 128
    int rg = tid >> 5;                            // 8 row-groups x 8 rows = 64
    int c0 = cg * 4;
    int r0 = rg * 8;

    float acc[8][4];
    #pragma unroll
    for (int r = 0; r < 8; r++)
        #pragma unroll
        for (int c = 0; c < 4; c++) acc[r][c] = 0.0f;

    #pragma unroll 4
    for (int k = 0; k < 64; k++) {
        float4 b4 = __ldg((const float4*)(W + k * 128 + c0));
        float a[8];
        #pragma unroll
        for (int r = 0; r < 8; r++) a[r] = sAf[(r0 + r) * 66 + k];   // broadcast
        #pragma unroll
        for (int r = 0; r < 8; r++) {
            acc[r][0] = fmaf(a[r], b4.x, acc[r][0]);
            acc[r][1] = fmaf(a[r], b4.y, acc[r][1]);
            acc[r][2] = fmaf(a[r], b4.z, acc[r][2]);
            acc[r][3] = fmaf(a[r], b4.w, acc[r][3]);
        }
    }

    float4 bb = *(const float4*)&bias[c0];
    #pragma unroll
    for (int r = 0; r < 8; r++) {
        float4 o;
        o.x = fmaxf(acc[r][0] + bb.x, 0.f);
        o.y = fmaxf(acc[r][1] + bb.y, 0.f);
        o.z = fmaxf(acc[r][2] + bb.z, 0.f);
        o.w = fmaxf(acc[r][3] + bb.w, 0.f);
        *(float4*)&Y[(row0 + r0 + r) * 128 + c0] = o;
    }
}

// ---------------- GEMM: Y[N,64] = X[N,128] @ W[128,64]  (no bias/relu) ----------------
__global__ void gemm2(const float* __restrict__ X, const float* __restrict__ W,
                      float* __restrict__ Y) {
    constexpr int K = 128, NC = 64, RT = 64, THREADS = 128;
    constexpr int XS = RT + 4;
    __shared__ float sX[K * XS];

    int tid = threadIdx.x;
    int row0 = blockIdx.x * RT;

    #pragma unroll 4
    for (int idx = tid; idx < RT * K; idx += THREADS) {
        int r = idx / K;
        int k = idx - r * K;
        sX[k * XS + r] = X[(row0 + r) * K + k];
    }
    __syncthreads();

    int cg = tid % (NC / 4);
    int rg = tid / (NC / 4);
    int c0 = cg * 4;
    int r0 = rg * 8;

    float acc[8][4];
    #pragma unroll
    for (int r = 0; r < 8; r++)
        #pragma unroll
        for (int c = 0; c < 4; c++) acc[r][c] = 0.0f;

    #pragma unroll 8
    for (int k = 0; k < K; k++) {
        float4 b4 = __ldg((const float4*)(W + k * NC + c0));
        float4 a0 = *(const float4*)&sX[k * XS + r0];
        float4 a1 = *(const float4*)&sX[k * XS + r0 + 4];
        float a[8] = {a0.x, a0.y, a0.z, a0.w, a1.x, a1.y, a1.z, a1.w};
        #pragma unroll
        for (int r = 0; r < 8; r++) {
            acc[r][0] = fmaf(a[r], b4.x, acc[r][0]);
            acc[r][1] = fmaf(a[r], b4.y, acc[r][1]);
            acc[r][2] = fmaf(a[r], b4.z, acc[r][2]);
            acc[r][3] = fmaf(a[r], b4.w, acc[r][3]);
        }
    }

    #pragma unroll
    for (int r = 0; r < 8; r++) {
        float4 o = make_float4(acc[r][0], acc[r][1], acc[r][2], acc[r][3]);
        *(float4*)&Y[(row0 + r0 + r) * NC + c0] = o;
    }
}

// ---------------- fused: agg(h2t) + bias + relu + FC + softmax, one block/graph ------
__global__ void agg_fc(const float* __restrict__ H, const float* __restrict__ Wfc,
                       const float* __restrict__ bfc, const float* __restrict__ b2,
                       float* __restrict__ out) {
    int g = blockIdx.x;
    int tid = threadIdx.x;                 // 256 = 8 warps
    int warp = tid >> 5, lane = tid & 31;
    const float2* H2 = (const float2*)H;

    float2 bb = ((const float2*)b2)[lane]; // feats {2*lane, 2*lane+1}

    float lg0 = 0.f, lg1 = 0.f, lg2 = 0.f, lg3 = 0.f;
    #pragma unroll 2
    for (int i = 0; i < 16; i++) {
        int nloc = warp * 16 + i;          // node within graph: 0..127
        int node = g * 128 + nloc;
        float2 acc = agg_node(H2, node, lane);
        float v0 = fmaxf(acc.x + bb.x, 0.f);
        float v1 = fmaxf(acc.y + bb.y, 0.f);
        float4 w0 = __ldg((const float4*)Wfc + nloc * 64 + 2 * lane);
        float4 w1 = __ldg((const float4*)Wfc + nloc * 64 + 2 * lane + 1);
        lg0 = fmaf(v0, w0.x, fmaf(v1, w1.x, lg0));
        lg1 = fmaf(v0, w0.y, fmaf(v1, w1.y, lg1));
        lg2 = fmaf(v0, w0.z, fmaf(v1, w1.z, lg2));
        lg3 = fmaf(v0, w0.w, fmaf(v1, w1.w, lg3));
    }

    #pragma unroll
    for (int off = 16; off > 0; off >>= 1) {
        lg0 += __shfl_xor_sync(0xffffffffu, lg0, off);
        lg1 += __shfl_xor_sync(0xffffffffu, lg1, off);
        lg2 += __shfl_xor_sync(0xffffffffu, lg2, off);
        lg3 += __shfl_xor_sync(0xffffffffu, lg3, off);
    }
    __shared__ float sred[8][4];
    if (lane == 0) {
        sred[warp][0] = lg0; sred[warp][1] = lg1;
        sred[warp][2] = lg2; sred[warp][3] = lg3;
    }
    __syncthreads();
    if (tid == 0) {
        float l[4];
        #pragma unroll
        for (int c = 0; c < 4; c++) {
            float s = bfc[c];
            #pragma unroll
            for (int w = 0; w < 8; w++) s += sred[w][c];
            l[c] = s;
        }
        float m = fmaxf(fmaxf(l[0], l[1]), fmaxf(l[2], l[3]));
        float e0 = __expf(l[0] - m), e1 = __expf(l[1] - m);
        float e2 = __expf(l[2] - m), e3 = __expf(l[3] - m);
        float inv = 1.0f / (e0 + e1 + e2 + e3);
        out[g * 4 + 0] = e0 * inv;
        out[g * 4 + 1] = e1 * inv;
        out[g * 4 + 2] = e2 * inv;
        out[g * 4 + 3] = e3 * inv;
    }
}

// ---------------- launch ----------------
extern "C" void kernel_launch(void* const* d_in, const int* in_sizes, int n_in,
                              void* d_out, int out_size) {
    const float* x   = (const float*)d_in[0];
    const int*   ei  = (const int*)d_in[1];
    const float* ew  = (const float*)d_in[2];
    const float* W1  = (const float*)d_in[3];
    const float* b1  = (const float*)d_in[4];
    const float* W2  = (const float*)d_in[5];
    const float* b2  = (const float*)d_in[6];
    const float* Wfc = (const float*)d_in[7];
    const float* bfc = (const float*)d_in[8];
    float* out = (float*)d_out;

    float* h1;  cudaGetSymbolAddress((void**)&h1, g_h1);
    float* h2t; cudaGetSymbolAddress((void**)&h2t, g_h2t);

    // normalization + CSR build
    k_init<<<NN / 256, 256>>>();
    k_deg_hist<<<EE / 256, 256>>>(ei, ew);
    k_scan1<<<128, 256>>>();
    k_scan2<<<1, 128>>>();
    k_scan3_dis<<<NN / 256, 256>>>();
    k_scatter<<<EE / 256, 256>>>(ei, ew);

    // layer 1 fused: aggregate(x) + GEMM(64->128) + bias + relu
    agg_gemm1<<<NN / 64, 256>>>(x, W1, b1, h1);

    // layer 2: GEMM(128->64); bias/relu deferred
    gemm2<<<NN / 64, 128>>>(h1, W2, h2t);

    // fused: aggregate(h2t) + bias + relu + FC + softmax
    agg_fc<<<1024, 256>>>(h2t, Wfc, bfc, b2, out);
}

// round 10
// speedup vs baseline: 1.4879x; 1.4879x over previous
#include <cuda_runtime.h>
#include <cuda_bf16.h>
#include <cstdint>

#define NN 131072
#define EE 2097152

// ---------------- device scratch (static; no allocation allowed) ----------------
__device__ float g_dis[NN];            // degree accumulator -> rsqrt(deg)
__device__ int   g_cnt[NN];            // in-degree histogram
__device__ int   g_rowptr[NN];         // exclusive scan of g_cnt
__device__ int   g_cur[NN];            // scatter cursor
__device__ int   g_blksum[128];
__device__ int   g_blkoff[128];
__device__ int2  g_csr[EE];            // (src, __float_as_int(norm)), grouped by dst
__device__ float g_aggx[NN * 64];      // A_norm @ x
__device__ float g_h1[NN * 128];       // relu(agg(x) @ W1 + b1)
__device__ float g_h2t[NN * 64];       // h1 @ W2
__device__ float g_h2[NN * 64];        // A_norm @ h2t

// ---------------- init + degree/histogram ----------------
__global__ void k_init() {
    int i = blockIdx.x * blockDim.x + threadIdx.x;
    if (i < NN) { g_dis[i] = 1.0f; g_cnt[i] = 0; }   // self-loop weight = 1
}

__global__ void k_deg_hist(const int* __restrict__ ei, const float* __restrict__ ew) {
    int e = blockIdx.x * blockDim.x + threadIdx.x;
    if (e < EE) {
        int d = ei[EE + e];
        atomicAdd(&g_dis[d], ew[e]);
        atomicAdd(&g_cnt[d], 1);
    }
}

// ---------------- exclusive scan of g_cnt (128 blocks x 1024 elems) ----------------
__global__ void k_scan1() {
    __shared__ int warp_s[8];
    int b = blockIdx.x, t = threadIdx.x;
    int base = b * 1024 + t * 4;
    int4 c = *(const int4*)&g_cnt[base];
    int s0 = c.x, s1 = s0 + c.y, s2 = s1 + c.z, s3 = s2 + c.w;
    int tsum = s3;
    int lane = t & 31, warp = t >> 5;
    int v = tsum;
    #pragma unroll
    for (int off = 1; off < 32; off <<= 1) {
        int u = __shfl_up_sync(0xffffffffu, v, off);
        if (lane >= off) v += u;
    }
    if (lane == 31) warp_s[warp] = v;
    __syncthreads();
    if (t < 8) {
        int x = warp_s[t];
        #pragma unroll
        for (int off = 1; off < 8; off <<= 1) {
            int u = __shfl_up_sync(0xffu, x, off);
            if (t >= off) x += u;
        }
        warp_s[t] = x;
    }
    __syncthreads();
    int woff = (warp > 0) ? warp_s[warp - 1] : 0;
    int texcl = woff + v - tsum;
    g_rowptr[base + 0] = texcl;
    g_rowptr[base + 1] = texcl + s0;
    g_rowptr[base + 2] = texcl + s1;
    g_rowptr[base + 3] = texcl + s2;
    if (t == 255) g_blksum[b] = woff + v;
}

__global__ void k_scan2() {
    __shared__ int sh[128];
    int t = threadIdx.x;
    int v = g_blksum[t];
    sh[t] = v;
    __syncthreads();
    for (int off = 1; off < 128; off <<= 1) {
        int u = (t >= off) ? sh[t - off] : 0;
        __syncthreads();
        sh[t] += u;
        __syncthreads();
    }
    g_blkoff[t] = sh[t] - v;   // exclusive
}

__global__ void k_scan3_dis() {
    int i = blockIdx.x * blockDim.x + threadIdx.x;
    if (i < NN) {
        int r = g_rowptr[i] + g_blkoff[i >> 10];
        g_rowptr[i] = r;
        g_cur[i] = r;
        g_dis[i] = rsqrtf(g_dis[i]);     // deg >= 1 (self-loop)
    }
}

// ---------------- scatter edges into CSR, norm computed inline ----------------
__global__ void k_scatter(const int* __restrict__ ei, const float* __restrict__ ew) {
    int e = blockIdx.x * blockDim.x + threadIdx.x;
    if (e >= EE) return;
    int s = ei[e], d = ei[EE + e];
    float nrm = g_dis[s] * ew[e] * g_dis[d];
    int pos = atomicAdd(&g_cur[d], 1);
    g_csr[pos] = make_int2(s, __float_as_int(nrm));
}

// ---------------- CSR gather aggregation: one warp per node, 64 feats ----------------
__global__ void k_agg_csr(const float* __restrict__ X, float* __restrict__ Out) {
    int warp = threadIdx.x >> 5;
    int lane = threadIdx.x & 31;
    int node = blockIdx.x * 8 + warp;
    const float2* X2 = (const float2*)X;

    float sn = g_dis[node];
    sn = sn * sn;
    float2 xs = X2[node * 32 + lane];
    float2 acc = make_float2(sn * xs.x, sn * xs.y);

    int beg = g_rowptr[node];
    int end = beg + g_cnt[node];
    #pragma unroll 4
    for (int j = beg; j < end; j++) {
        int2 pr = g_csr[j];                       // uniform -> broadcast
        float nrm = __int_as_float(pr.y);
        float2 v = X2[pr.x * 32 + lane];          // coalesced 256B gather
        acc.x = fmaf(nrm, v.x, acc.x);
        acc.y = fmaf(nrm, v.y, acc.y);
    }
    ((float2*)Out)[node * 32 + lane] = acc;
}

// ---------------- tf32 tensor-core GEMM: Y[N,NC] = X[N,K] @ W[K,NC] ----------------
__device__ __forceinline__ unsigned int cvt_tf32(float f) {
    unsigned int o;
    asm("cvt.rna.tf32.f32 %0, %1;" : "=r"(o) : "f"(f));
    return o;
}

__device__ __forceinline__ void mma_tf32(float* c, unsigned int a0, unsigned int a1,
                                         unsigned int a2, unsigned int a3,
                                         unsigned int b0, unsigned int b1) {
    asm volatile("mma.sync.aligned.m16n8k8.row.col.f32.tf32.tf32.f32 "
                 "{%0,%1,%2,%3}, {%4,%5,%6,%7}, {%8,%9}, {%0,%1,%2,%3};"
                 : "+f"(c[0]), "+f"(c[1]), "+f"(c[2]), "+f"(c[3])
                 : "r"(a0), "r"(a1), "r"(a2), "r"(a3), "r"(b0), "r"(b1));
}

// Block: 256 threads (8 warps), tile 128 rows x NC cols. Warp w owns rows [w*16, w*16+16).
// Padding: SX=K+4 -> A-frag LDS bank = (4*row + k) % 32, conflict-free.
//          SW=NC+8 -> B-frag LDS bank = (8*k + n) % 32, conflict-free.
template<int K, int NC, bool BIAS_RELU>
__global__ void gemm_tc(const float* __restrict__ X, const float* __restrict__ W,
                        const float* __restrict__ bias, float* __restrict__ Y) {
    constexpr int SX = K + 4;
    constexpr int SW = NC + 8;
    constexpr int NT = NC / 8;
    extern __shared__ float smem[];
    float* sX = smem;               // 128 * SX
    float* sW = smem + 128 * SX;    // K * SW

    int tid = threadIdx.x, lane = tid & 31, warp = tid >> 5;
    int row0 = blockIdx.x * 128;

    // stage X tile (128 x K) and W (K x NC), float4
    #pragma unroll 4
    for (int idx = tid; idx < 128 * (K / 4); idx += 256) {
        int r = idx / (K / 4);
        int c4 = idx % (K / 4);
        float4 v = ((const float4*)(X + (size_t)(row0 + r) * K))[c4];
        *(float4*)&sX[r * SX + c4 * 4] = v;
    }
    #pragma unroll 4
    for (int idx = tid; idx < K * (NC / 4); idx += 256) {
        int r = idx / (NC / 4);
        int c4 = idx % (NC / 4);
        float4 v = ((const float4*)(W + r * NC))[c4];
        *(float4*)&sW[r * SW + c4 * 4] = v;
    }
    __syncthreads();

    float acc[NT][4];
    #pragma unroll
    for (int t = 0; t < NT; t++)
        #pragma unroll
        for (int i = 0; i < 4; i++) acc[t][i] = 0.0f;

    int ar = warp * 16 + (lane >> 2);   // A rows: ar, ar+8
    int ak = lane & 3;                  // A col base within k-step
    int bk = lane & 3;                  // B k base
    int bn = lane >> 2;                 // B n within tile

    #pragma unroll
    for (int ks = 0; ks < K / 8; ks++) {
        int k0 = ks * 8;
        unsigned int a0 = cvt_tf32(sX[ar * SX + k0 + ak]);
        unsigned int a1 = cvt_tf32(sX[(ar + 8) * SX + k0 + ak]);
        unsigned int a2 = cvt_tf32(sX[ar * SX + k0 + ak + 4]);
        unsigned int a3 = cvt_tf32(sX[(ar + 8) * SX + k0 + ak + 4]);
        #pragma unroll
        for (int t = 0; t < NT; t++) {
            unsigned int b0 = cvt_tf32(sW[(k0 + bk) * SW + t * 8 + bn]);
            unsigned int b1 = cvt_tf32(sW[(k0 + bk + 4) * SW + t * 8 + bn]);
            mma_tf32(acc[t], a0, a1, a2, a3, b0, b1);
        }
    }

    // epilogue: thread owns rows (ar, ar+8), cols t*8 + 2*(lane&3) .. +1
    int orow = row0 + ar;
    #pragma unroll
    for (int t = 0; t < NT; t++) {
        int col = t * 8 + 2 * (lane & 3);
        float b0 = 0.f, b1 = 0.f;
        if (BIAS_RELU) { b0 = bias[col]; b1 = bias[col + 1]; }
        float2 v0 = make_float2(acc[t][0] + b0, acc[t][1] + b1);
        float2 v1 = make_float2(acc[t][2] + b0, acc[t][3] + b1);
        if (BIAS_RELU) {
            v0.x = fmaxf(v0.x, 0.f); v0.y = fmaxf(v0.y, 0.f);
            v1.x = fmaxf(v1.x, 0.f); v1.y = fmaxf(v1.y, 0.f);
        }
        *(float2*)&Y[(size_t)orow * NC + col] = v0;
        *(float2*)&Y[(size_t)(orow + 8) * NC + col] = v1;
    }
}

// ---------------- FC + softmax (fuses layer-2 bias + relu) ----------------
__global__ void fc_softmax(const float* __restrict__ H, const float* __restrict__ Wfc,
                           const float* __restrict__ bfc, const float* __restrict__ b2,
                           float* __restrict__ out) {
    int g = blockIdx.x;
    int tid = threadIdx.x;      // 256
    const float* hrow = H + g * 8192;

    float a0 = 0.f, a1 = 0.f, a2 = 0.f, a3 = 0.f;
    for (int j = tid; j < 8192; j += 256) {
        float v = hrow[j] + b2[j & 63];
        v = fmaxf(v, 0.f);
        float4 w = __ldg((const float4*)Wfc + j);
        a0 = fmaf(v, w.x, a0);
        a1 = fmaf(v, w.y, a1);
        a2 = fmaf(v, w.z, a2);
        a3 = fmaf(v, w.w, a3);
    }
    #pragma unroll
    for (int off = 16; off > 0; off >>= 1) {
        a0 += __shfl_xor_sync(0xffffffffu, a0, off);
        a1 += __shfl_xor_sync(0xffffffffu, a1, off);
        a2 += __shfl_xor_sync(0xffffffffu, a2, off);
        a3 += __shfl_xor_sync(0xffffffffu, a3, off);
    }
    __shared__ float sred[8][4];
    int lane = tid & 31, warp = tid >> 5;
    if (lane == 0) {
        sred[warp][0] = a0; sred[warp][1] = a1;
        sred[warp][2] = a2; sred[warp][3] = a3;
    }
    __syncthreads();
    if (tid == 0) {
        float l[4];
        #pragma unroll
        for (int c = 0; c < 4; c++) {
            float s = bfc[c];
            #pragma unroll
            for (int w = 0; w < 8; w++) s += sred[w][c];
            l[c] = s;
        }
        float m = fmaxf(fmaxf(l[0], l[1]), fmaxf(l[2], l[3]));
        float e0 = __expf(l[0] - m), e1 = __expf(l[1] - m);
        float e2 = __expf(l[2] - m), e3 = __expf(l[3] - m);
        float inv = 1.0f / (e0 + e1 + e2 + e3);
        out[g * 4 + 0] = e0 * inv;
        out[g * 4 + 1] = e1 * inv;
        out[g * 4 + 2] = e2 * inv;
        out[g * 4 + 3] = e3 * inv;
    }
}

// ---------------- launch ----------------
extern "C" void kernel_launch(void* const* d_in, const int* in_sizes, int n_in,
                              void* d_out, int out_size) {
    const float* x   = (const float*)d_in[0];
    const int*   ei  = (const int*)d_in[1];
    const float* ew  = (const float*)d_in[2];
    const float* W1  = (const float*)d_in[3];
    const float* b1  = (const float*)d_in[4];
    const float* W2  = (const float*)d_in[5];
    const float* b2  = (const float*)d_in[6];
    const float* Wfc = (const float*)d_in[7];
    const float* bfc = (const float*)d_in[8];
    float* out = (float*)d_out;

    float* aggx; cudaGetSymbolAddress((void**)&aggx, g_aggx);
    float* h1;   cudaGetSymbolAddress((void**)&h1, g_h1);
    float* h2t;  cudaGetSymbolAddress((void**)&h2t, g_h2t);
    float* h2;   cudaGetSymbolAddress((void**)&h2, g_h2);

    // dynamic smem: gemm1 = 128*68 + 64*136 floats; gemm2 = 128*132 + 128*72 floats
    const int smem1 = (128 * 68 + 64 * 136) * 4;
    const int smem2 = (128 * 132 + 128 * 72) * 4;
    cudaFuncSetAttribute(gemm_tc<64, 128, true>,
                         cudaFuncAttributeMaxDynamicSharedMemorySize, smem1);
    cudaFuncSetAttribute(gemm_tc<128, 64, false>,
                         cudaFuncAttributeMaxDynamicSharedMemorySize, smem2);

    // normalization + CSR build
    k_init<<<NN / 256, 256>>>();
    k_deg_hist<<<EE / 256, 256>>>(ei, ew);
    k_scan1<<<128, 256>>>();
    k_scan2<<<1, 128>>>();
    k_scan3_dis<<<NN / 256, 256>>>();
    k_scatter<<<EE / 256, 256>>>(ei, ew);

    // layer 1: aggregate x (64 feats), then TC GEMM (64->128) + bias + relu
    k_agg_csr<<<NN / 8, 256>>>(x, aggx);
    gemm_tc<64, 128, true><<<NN / 128, 256, smem1>>>(aggx, W1, b1, h1);

    // layer 2: TC GEMM (128->64), then aggregate; bias/relu deferred to FC
    gemm_tc<128, 64, false><<<NN / 128, 256, smem2>>>(h1, W2, nullptr, h2t);
    k_agg_csr<<<NN / 8, 256>>>(h2t, h2);

    // FC + softmax
    fc_softmax<<<1024, 256>>>(h2, Wfc, bfc, b2, out);
}